// round 14
// baseline (speedup 1.0000x reference)
#include <cuda_runtime.h>
#include <cuda_bf16.h>
#include <cstdint>

// Problem constants
#define TT   1024
#define BB   32
#define NH   8
#define DD   32
#define YD   97
#define INDIM 256          // NH*DD
#define ROWSTRIDE 8192     // BB*INDIM

typedef unsigned long long u64;

// -------- scratch (device globals; no allocation allowed) ----------
__device__ float g_fwm[(size_t)TT * BB * INDIM];   // FWM output pre-GEMM, 33.5 MB

// -------- named barriers ----------
#define BAR_SYNC(id, cnt)   asm volatile("bar.sync %0, %1;"   :: "r"(id), "r"(cnt) : "memory")
#define BAR_ARRIVE(id, cnt) asm volatile("bar.arrive %0, %1;" :: "r"(id), "r"(cnt) : "memory")

// -------- packed f32x2 helpers ----------
__device__ __forceinline__ u64 ffma2(u64 a, u64 b, u64 c) {
    u64 d;
    asm("fma.rn.f32x2 %0, %1, %2, %3;" : "=l"(d) : "l"(a), "l"(b), "l"(c));
    return d;
}
__device__ __forceinline__ u64 add2(u64 a, u64 b) {
    u64 d;
    asm("add.rn.f32x2 %0, %1, %2;" : "=l"(d) : "l"(a), "l"(b));
    return d;
}
__device__ __forceinline__ u64 pack2(float a, float b) {
    u64 r;
    asm("mov.b64 %0, {%1, %2};" : "=l"(r) : "f"(a), "f"(b));
    return r;
}
__device__ __forceinline__ u64 bcast2(float a) {
    u64 r;
    asm("mov.b64 %0, {%1, %1};" : "=l"(r) : "f"(a));
    return r;
}
__device__ __forceinline__ float hsum2(u64 v) {
    float a, b;
    asm("mov.b64 {%0, %1}, %2;" : "=f"(a), "=f"(b) : "l"(v));
    return a + b;
}

union f4u {
    float4 f;
    u64    u[2];
};
__device__ __forceinline__ f4u ld4(const float* p) {
    f4u r;
    r.f = *(const float4*)p;   // LDS.128
    return r;
}

__device__ __forceinline__ float wsum(float v) {
#pragma unroll
    for (int o = 16; o; o >>= 1) v += __shfl_xor_sync(0xffffffffu, v, o);
    return v;
}

__device__ __forceinline__ float hsum4(const u64* a) {
    return hsum2(add2(add2(a[0], a[1]), add2(a[2], a[3])));
}

// -------- dot(x, column) via 8 LDS.128 + 16 FFMA2 --------
__device__ __forceinline__ float dot32v(const float* __restrict__ xp, const u64* c) {
    u64 a0 = 0ull, a1 = 0ull, a2 = 0ull, a3 = 0ull;
#pragma unroll
    for (int i = 0; i < 4; i++) {
        f4u x0 = ld4(xp + 8 * i);
        f4u x1 = ld4(xp + 8 * i + 4);
        a0 = ffma2(x0.u[0], c[4 * i],     a0);
        a1 = ffma2(x0.u[1], c[4 * i + 1], a1);
        a2 = ffma2(x1.u[0], c[4 * i + 2], a2);
        a3 = ffma2(x1.u[1], c[4 * i + 3], a3);
    }
    return hsum2(add2(add2(a0, a1), add2(a2, a3)));
}

// -------- one SRWM column step on c_old: returns yv, fills kv, sets delta --
__device__ __forceinline__ float col_step(const u64* c, u64* kv,
                                          const float* __restrict__ qp,
                                          const float* __restrict__ kp,
                                          const float* __restrict__ xp,
                                          float bi, float sxk, float& delta) {
    const u64 neg1 = bcast2(-1.0f);
    u64 ad[4] = {0ull, 0ull, 0ull, 0ull};
    u64 ax[4] = {0ull, 0ull, 0ull, 0ull};
#pragma unroll
    for (int i = 0; i < 8; i++) {
        f4u qv = ld4(qp + 4 * i);
        f4u kk = ld4(kp + 4 * i);
        f4u xv = ld4(xp + 4 * i);
        u64 dm0 = ffma2(kk.u[0], neg1, qv.u[0]);   // q - k
        u64 dm1 = ffma2(kk.u[1], neg1, qv.u[1]);
        ad[(2 * i)     & 3] = ffma2(dm0, c[2 * i],     ad[(2 * i)     & 3]);
        ad[(2 * i + 1) & 3] = ffma2(dm1, c[2 * i + 1], ad[(2 * i + 1) & 3]);
        ax[(2 * i)     & 3] = ffma2(xv.u[0], c[2 * i],     ax[(2 * i)     & 3]);
        ax[(2 * i + 1) & 3] = ffma2(xv.u[1], c[2 * i + 1], ax[(2 * i + 1) & 3]);
        kv[2 * i]     = kk.u[0];
        kv[2 * i + 1] = kk.u[1];
    }
    delta = bi * hsum4(ad);
    return hsum4(ax) + delta * sxk;
}

// ======================================================================
// Kernel 1: fused softmax(h) + SRWM + FWM recurrence. One CTA per (b,h).
// Decoupled barrier groups:
//   group2 (recurrence): w3 (beta/fb), w4 (q), w5 (k), w7 (x staging)
//       per step: publish -> bar.sync(1,128) -> bar.arrive(3+(t&3),256)
//   group1 (pipeline):   w0 (fq), w1 (fk), w2 (fv), w6 (FWM+STG)
//       per step: bar.sync(3+(t&3),256) -> compute -> bar.sync(2,128)
// Cross-group buffers are 8-deep rings; full __syncthreads every 4 steps
// bounds skew (<4) so rings and rotating barriers are safe.
// ======================================================================
__global__ __launch_bounds__(256, 2)
void srwm_kernel(const float* __restrict__ h,
                 const float* __restrict__ W_y, const float* __restrict__ W_q,
                 const float* __restrict__ W_k, const float* __restrict__ w_b,
                 const float* __restrict__ sW_y, const float* __restrict__ sW_q,
                 const float* __restrict__ sW_k, const float* __restrict__ sw_b,
                 const float* __restrict__ F0) {
    __shared__ __align__(16) float xs[8][DD];
    __shared__ __align__(16) float q_s[8][DD], k_s[8][DD];
    __shared__ __align__(16) float beta_s[8][4];
    __shared__ float fb_s[8];
    __shared__ __align__(16) float fq_s[2][DD], fk_s[2][DD], fv_s[2][DD];

    const int bh   = blockIdx.x;           // b*NH + h
    const int hh   = bh & (NH - 1);
    const int tid  = threadIdx.x;
    const int warp = tid >> 5;
    const int lane = tid & 31;

    // ---- column assignment ----
    // w0,w1,w2: Wy cols warp*32+lane (-> fq,fk,fv; beta idx 0)
    // w3: lane0 Wy col 96 (-> fb, beta idx 0); lanes>=1 wb col (lane-1)&3 (beta idx 3)
    // w4: Wq (beta idx 1)   w5: Wk (beta idx 2)   w6: F   w7: none
    u64 c[16];
#pragma unroll
    for (int i = 0; i < 16; i++) c[i] = 0ull;
    if (warp <= 6) {
        const float* sp;
        const float* wp = nullptr;
        int stride;
        if (warp < 3) {
            int e = warp * 32 + lane;
            sp = sW_y + (size_t)bh * DD * YD + e; wp = W_y + (size_t)hh * DD * YD + e; stride = YD;
        } else if (warp == 3) {
            if (lane == 0) { sp = sW_y + (size_t)bh * DD * YD + 96; wp = W_y + (size_t)hh * DD * YD + 96; stride = YD; }
            else { int e = (lane - 1) & 3;
                   sp = sw_b + (size_t)bh * DD * 4 + e; wp = w_b + (size_t)hh * DD * 4 + e; stride = 4; }
        } else if (warp == 4) {
            sp = sW_q + (size_t)bh * DD * DD + lane; wp = W_q + (size_t)hh * DD * DD + lane; stride = DD;
        } else if (warp == 5) {
            sp = sW_k + (size_t)bh * DD * DD + lane; wp = W_k + (size_t)hh * DD * DD + lane; stride = DD;
        } else {
            sp = F0 + (size_t)bh * DD * DD + lane; stride = DD;
        }
#pragma unroll
        for (int i = 0; i < 16; i++) {
            float v0 = sp[(2 * i)     * stride];
            float v1 = sp[(2 * i + 1) * stride];
            if (wp) { v0 += wp[(2 * i) * stride]; v1 += wp[(2 * i + 1) * stride]; }
            c[i] = pack2(v0, v1);
        }
    }

    // ---- prologue: w7 stages x0; fills 2-deep LDG pipe (h1, h2) ----
    const float* hrow = h + (size_t)bh * DD + lane;
    float xr0 = 0.0f, xr1 = 0.0f;
    float* gout = g_fwm + (size_t)bh * DD + lane;
    if (warp == 7) {
        float p = __expf(hrow[0]);
        float s = wsum(p);
        xs[0][lane] = __fdividef(p, s);
        xr0 = hrow[ROWSTRIDE];
        xr1 = hrow[(size_t)2 * ROWSTRIDE];
    }
    __syncthreads();

    const bool g2 = (warp == 3) || (warp == 4) || (warp == 5) || (warp == 7);
    const int bidx = (warp == 4) ? 1 : (warp == 5) ? 2 : 0;   // w0-2 use 0
    const int bidx3 = (lane == 0) ? 0 : 3;                    // w3 per-lane

    // ---- peeled iteration t = 0 ----
    if (g2) {
        if (warp != 7) {
            float yv = dot32v(xs[0], c);
            if (warp == 3) {
                float sg = __fdividef(1.0f, 1.0f + __expf(-yv));
                if (lane == 0) fb_s[0] = sg;
                else if (lane <= 4) beta_s[0][lane - 1] = sg;
            } else if (warp == 4) {
                float p = __expf(yv); float s = wsum(p); q_s[0][lane] = __fdividef(p, s);
            } else {
                float p = __expf(yv); float s = wsum(p); k_s[0][lane] = __fdividef(p, s);
            }
        } else {
            float p = __expf(xr0);
            float s = wsum(p);
            xs[1][lane] = __fdividef(p, s);
            xr0 = xr1;
            xr1 = hrow[(size_t)3 * ROWSTRIDE];
        }
        BAR_SYNC(1, 128);
        BAR_ARRIVE(3, 256);
    } else {
        BAR_SYNC(3, 256);
        if (warp < 3) {
            float yv = dot32v(xs[0], c);
            if (warp == 0)      { float p = __expf(yv); float s = wsum(p); fq_s[0][lane] = __fdividef(p, s); }
            else if (warp == 1) { float p = __expf(yv); float s = wsum(p); fk_s[0][lane] = __fdividef(p, s); }
            else                { fv_s[0][lane] = yv; }
        }
        BAR_SYNC(2, 128);
    }

    // ================= time loop =================
    for (int t = 1; t < TT; t++) {
        if ((t & 3) == 0) __syncthreads();    // skew bound (all warps)

        const int rm = (t - 1) & 7;
        const int rt = t & 7;
        const int pm = (t - 1) & 1;
        const int pc = t & 1;
        const int bcr = 3 + (t & 3);          // rotating cross barrier id

        if (g2) {
            if (warp != 7) {
                const float* qp = q_s[rm];
                const float* kp = k_s[rm];
                const float* xp = xs[rt];
                float sxk = wsum(xp[lane] * kp[lane]);
                float bi  = beta_s[rm][(warp == 3) ? bidx3 : bidx];
                u64 kv[16];
                float delta;
                float yv = col_step(c, kv, qp, kp, xp, bi, sxk, delta);

                if (warp == 3) {
                    float sg = __fdividef(1.0f, 1.0f + __expf(-yv));
                    if (lane == 0) fb_s[rt] = sg;
                    else if (lane <= 4) beta_s[rt][lane - 1] = sg;
                } else if (warp == 4) {
                    float p = __expf(yv); float s = wsum(p); q_s[rt][lane] = __fdividef(p, s);
                } else {
                    float p = __expf(yv); float s = wsum(p); k_s[rt][lane] = __fdividef(p, s);
                }
                BAR_SYNC(1, 128);
                BAR_ARRIVE(bcr, 256);
                // state update off the published path
                u64 d2 = bcast2(delta);
#pragma unroll
                for (int i = 0; i < 16; i++) c[i] = ffma2(kv[i], d2, c[i]);
            } else {
                if (t + 1 < TT) {
                    float p = __expf(xr0);
                    float s = wsum(p);
                    xs[(t + 1) & 7][lane] = __fdividef(p, s);
                    xr0 = xr1;
                    xr1 = (t + 3 < TT) ? hrow[(size_t)(t + 3) * ROWSTRIDE] : 0.0f;
                }
                BAR_SYNC(1, 128);
                BAR_ARRIVE(bcr, 256);
            }
        } else {
            BAR_SYNC(bcr, 256);   // wait for group2's step-t publications
            if (warp < 3) {
                const float* qp = q_s[rm];
                const float* kp = k_s[rm];
                const float* xp = xs[rt];
                float sxk = wsum(xp[lane] * kp[lane]);
                float bi  = beta_s[rm][0];
                u64 kv[16];
                float delta;
                float yv = col_step(c, kv, qp, kp, xp, bi, sxk, delta);

                if (warp == 0)      { float p = __expf(yv); float s = wsum(p); fq_s[pc][lane] = __fdividef(p, s); }
                else if (warp == 1) { float p = __expf(yv); float s = wsum(p); fk_s[pc][lane] = __fdividef(p, s); }
                else                { fv_s[pc][lane] = yv; }
                BAR_SYNC(2, 128);
                u64 d2 = bcast2(delta);
#pragma unroll
                for (int i = 0; i < 16; i++) c[i] = ffma2(kv[i], d2, c[i]);
            } else {
                // ---- w6: FWM step t-1 ----
                const float* fqp = fq_s[pm];
                const float* fkp = fk_s[pm];
                float sqk = wsum(fqp[lane] * fkp[lane]);
                float fb  = fb_s[rm];
                float fvd = fv_s[pm][lane];

                u64 kv[16];
                u64 av[4] = {0ull, 0ull, 0ull, 0ull};
                u64 ao[4] = {0ull, 0ull, 0ull, 0ull};
#pragma unroll
                for (int i = 0; i < 8; i++) {
                    f4u fqv = ld4(fqp + 4 * i);
                    f4u fkv = ld4(fkp + 4 * i);
                    av[(2 * i)     & 3] = ffma2(fkv.u[0], c[2 * i],     av[(2 * i)     & 3]);
                    av[(2 * i + 1) & 3] = ffma2(fkv.u[1], c[2 * i + 1], av[(2 * i + 1) & 3]);
                    ao[(2 * i)     & 3] = ffma2(fqv.u[0], c[2 * i],     ao[(2 * i)     & 3]);
                    ao[(2 * i + 1) & 3] = ffma2(fqv.u[1], c[2 * i + 1], ao[(2 * i + 1) & 3]);
                    kv[2 * i]     = fkv.u[0];
                    kv[2 * i + 1] = fkv.u[1];
                }
                float vold = hsum4(av);
                float outq = hsum4(ao);
                float delta = fb * (fvd - vold);
                gout[(size_t)(t - 1) * ROWSTRIDE] = outq + delta * sqk;
                u64 d2 = bcast2(delta);
#pragma unroll
                for (int i = 0; i < 16; i++) c[i] = ffma2(kv[i], d2, c[i]);
                BAR_SYNC(2, 128);
            }
        }
    }

    // ---- epilogue: w6 FWM step TT-1 ----
    if (warp == 6) {
        const int pm = (TT - 1) & 1;
        const float* fqp = fq_s[pm];
        const float* fkp = fk_s[pm];
        float sqk = wsum(fqp[lane] * fkp[lane]);
        float fb  = fb_s[(TT - 1) & 7];
        float fvd = fv_s[pm][lane];
        u64 av[4] = {0ull, 0ull, 0ull, 0ull};
        u64 ao[4] = {0ull, 0ull, 0ull, 0ull};
#pragma unroll
        for (int i = 0; i < 8; i++) {
            f4u fqv = ld4(fqp + 4 * i);
            f4u fkv = ld4(fkp + 4 * i);
            av[(2 * i)     & 3] = ffma2(fkv.u[0], c[2 * i],     av[(2 * i)     & 3]);
            av[(2 * i + 1) & 3] = ffma2(fkv.u[1], c[2 * i + 1], av[(2 * i + 1) & 3]);
            ao[(2 * i)     & 3] = ffma2(fqv.u[0], c[2 * i],     ao[(2 * i)     & 3]);
            ao[(2 * i + 1) & 3] = ffma2(fqv.u[1], c[2 * i + 1], ao[(2 * i + 1) & 3]);
        }
        float vold = hsum4(av);
        float outq = hsum4(ao);
        float delta = fb * (fvd - vold);
        gout[(size_t)(TT - 1) * ROWSTRIDE] = outq + delta * sqk;
    }
}

// ======================================================================
// Kernel 2: out = h + g_fwm @ W_out^T    (M=32768, N=256, K=256)
// (unchanged from the 801us best)
// ======================================================================
#define GBM 128
#define GBN 64
#define GBK 32
#define ALDA (GBM + 4)
#define BLDA (GBN + 4)

__global__ __launch_bounds__(256)
void out_gemm_kernel(const float* __restrict__ W,   // W_out [n][k], 256x256
                     const float* __restrict__ h,
                     float* __restrict__ out) {
    __shared__ __align__(16) float As[2][GBK][ALDA];
    __shared__ __align__(16) float Bs[2][GBK][BLDA];

    const int tid = threadIdx.x;
    const int m0  = blockIdx.x * GBM;
    const int n0  = blockIdx.y * GBN;
    const int ty  = tid >> 4;
    const int tx  = tid & 15;

    const int a_row = tid >> 3;
    const int a_kv  = (tid & 7) * 4;
    const int b_row = tid >> 3;
    const int b_kv  = (tid & 7) * 4;

    u64 acc[8][2];
#pragma unroll
    for (int i = 0; i < 8; i++) { acc[i][0] = 0ull; acc[i][1] = 0ull; }

    const int NT = INDIM / GBK;

    float4 ar[4], br[2];
#pragma unroll
    for (int r = 0; r < 4; r++)
        ar[r] = *(const float4*)(g_fwm + (size_t)(m0 + a_row + r * 32) * INDIM + a_kv);
#pragma unroll
    for (int r = 0; r < 2; r++)
        br[r] = *(const float4*)(W + (size_t)(n0 + b_row + r * 32) * INDIM + b_kv);
#pragma unroll
    for (int r = 0; r < 4; r++) {
        int row = a_row + r * 32;
        As[0][a_kv + 0][row] = ar[r].x; As[0][a_kv + 1][row] = ar[r].y;
        As[0][a_kv + 2][row] = ar[r].z; As[0][a_kv + 3][row] = ar[r].w;
    }
#pragma unroll
    for (int r = 0; r < 2; r++) {
        int row = b_row + r * 32;
        Bs[0][b_kv + 0][row] = br[r].x; Bs[0][b_kv + 1][row] = br[r].y;
        Bs[0][b_kv + 2][row] = br[r].z; Bs[0][b_kv + 3][row] = br[r].w;
    }
    __syncthreads();

    for (int kt = 0; kt < NT; kt++) {
        const int s = kt & 1;
        if (kt + 1 < NT) {
            const int ko = (kt + 1) * GBK;
#pragma unroll
            for (int r = 0; r < 4; r++)
                ar[r] = *(const float4*)(g_fwm + (size_t)(m0 + a_row + r * 32) * INDIM + ko + a_kv);
#pragma unroll
            for (int r = 0; r < 2; r++)
                br[r] = *(const float4*)(W + (size_t)(n0 + b_row + r * 32) * INDIM + ko + b_kv);
        }
#pragma unroll
        for (int k = 0; k < GBK; k++) {
            f4u a0 = ld4(&As[s][k][ty * 8]);
            f4u a1 = ld4(&As[s][k][ty * 8 + 4]);
            f4u b  = ld4(&Bs[s][k][tx * 4]);
            u64 p;
            float av[8];
            av[0] = a0.f.x; av[1] = a0.f.y; av[2] = a0.f.z; av[3] = a0.f.w;
            av[4] = a1.f.x; av[5] = a1.f.y; av[6] = a1.f.z; av[7] = a1.f.w;
#pragma unroll
            for (int i = 0; i < 8; i++) {
                p = bcast2(av[i]);
                acc[i][0] = ffma2(p, b.u[0], acc[i][0]);
                acc[i][1] = ffma2(p, b.u[1], acc[i][1]);
            }
        }
        if (kt + 1 < NT) {
            const int d = s ^ 1;
#pragma unroll
            for (int r = 0; r < 4; r++) {
                int row = a_row + r * 32;
                As[d][a_kv + 0][row] = ar[r].x; As[d][a_kv + 1][row] = ar[r].y;
                As[d][a_kv + 2][row] = ar[r].z; As[d][a_kv + 3][row] = ar[r].w;
            }
#pragma unroll
            for (int r = 0; r < 2; r++) {
                int row = b_row + r * 32;
                Bs[d][b_kv + 0][row] = br[r].x; Bs[d][b_kv + 1][row] = br[r].y;
                Bs[d][b_kv + 2][row] = br[r].z; Bs[d][b_kv + 3][row] = br[r].w;
            }
            __syncthreads();
        }
    }

#pragma unroll
    for (int i = 0; i < 8; i++) {
        int row = m0 + ty * 8 + i;
        const float* hp = h + (size_t)row * INDIM + n0 + tx * 4;
        float4 hv = *(const float4*)hp;
        float a, b, cc, d;
        asm("mov.b64 {%0, %1}, %2;" : "=f"(a), "=f"(b) : "l"(acc[i][0]));
        asm("mov.b64 {%0, %1}, %2;" : "=f"(cc), "=f"(d) : "l"(acc[i][1]));
        float4 o;
        o.x = hv.x + a; o.y = hv.y + b; o.z = hv.z + cc; o.w = hv.w + d;
        *(float4*)(out + (size_t)row * INDIM + n0 + tx * 4) = o;
    }
}

// ======================================================================
extern "C" void kernel_launch(void* const* d_in, const int* in_sizes, int n_in,
                              void* d_out, int out_size) {
    const float* h     = (const float*)d_in[0];
    const float* W_y   = (const float*)d_in[1];
    const float* W_q   = (const float*)d_in[2];
    const float* W_k   = (const float*)d_in[3];
    const float* w_b   = (const float*)d_in[4];
    const float* W_out = (const float*)d_in[5];
    const float* sW_y  = (const float*)d_in[6];
    const float* sW_q  = (const float*)d_in[7];
    const float* sW_k  = (const float*)d_in[8];
    const float* sw_b  = (const float*)d_in[9];
    const float* F0    = (const float*)d_in[10];
    float* out = (float*)d_out;

    srwm_kernel<<<BB * NH, 256>>>(h, W_y, W_q, W_k, w_b, sW_y, sW_q, sW_k, sw_b, F0);

    dim3 ggrid((TT * BB) / GBM, INDIM / GBN);
    out_gemm_kernel<<<ggrid, 256>>>(W_out, h, out);
}

// round 16
// speedup vs baseline: 1.0612x; 1.0612x over previous
#include <cuda_runtime.h>
#include <cuda_bf16.h>
#include <cstdint>

// Problem constants
#define TT   1024
#define BB   32
#define NH   8
#define DD   32
#define YD   97
#define INDIM 256          // NH*DD
#define ROWSTRIDE 8192     // BB*INDIM

typedef unsigned long long u64;

// -------- scratch (device globals; no allocation allowed) ----------
__device__ float g_fwm[(size_t)TT * BB * INDIM];   // FWM output pre-GEMM, 33.5 MB

// -------- packed f32x2 helpers ----------
__device__ __forceinline__ u64 ffma2(u64 a, u64 b, u64 c) {
    u64 d;
    asm("fma.rn.f32x2 %0, %1, %2, %3;" : "=l"(d) : "l"(a), "l"(b), "l"(c));
    return d;
}
__device__ __forceinline__ u64 add2(u64 a, u64 b) {
    u64 d;
    asm("add.rn.f32x2 %0, %1, %2;" : "=l"(d) : "l"(a), "l"(b));
    return d;
}
__device__ __forceinline__ u64 pack2(float a, float b) {
    u64 r;
    asm("mov.b64 %0, {%1, %2};" : "=l"(r) : "f"(a), "f"(b));
    return r;
}
__device__ __forceinline__ u64 bcast2(float a) {
    u64 r;
    asm("mov.b64 %0, {%1, %1};" : "=l"(r) : "f"(a));
    return r;
}
__device__ __forceinline__ float hsum2(u64 v) {
    float a, b;
    asm("mov.b64 {%0, %1}, %2;" : "=f"(a), "=f"(b) : "l"(v));
    return a + b;
}

// float4 viewed as two packed f32x2
union f4u {
    float4 f;
    u64    u[2];
};
__device__ __forceinline__ f4u ld4(const float* p) {
    f4u r;
    r.f = *(const float4*)p;   // LDS.128
    return r;
}

// -------- warp sum (5-round SHFL butterfly; f32 REDUX absent on sm_103) ----
__device__ __forceinline__ float wsum(float v) {
#pragma unroll
    for (int o = 16; o; o >>= 1) v += __shfl_xor_sync(0xffffffffu, v, o);
    return v;
}

__device__ __forceinline__ float hsum4(const u64* a) {
    return hsum2(add2(add2(a[0], a[1]), add2(a[2], a[3])));
}

// -------- dot(x[0:32], column) via 8 LDS.128 + 16 FFMA2 (peel only) --------
__device__ __forceinline__ float dot32v(const float* __restrict__ xp, const u64* c) {
    u64 a0 = 0ull, a1 = 0ull, a2 = 0ull, a3 = 0ull;
#pragma unroll
    for (int i = 0; i < 4; i++) {
        f4u x0 = ld4(xp + 8 * i);
        f4u x1 = ld4(xp + 8 * i + 4);
        a0 = ffma2(x0.u[0], c[4 * i],     a0);
        a1 = ffma2(x0.u[1], c[4 * i + 1], a1);
        a2 = ffma2(x1.u[0], c[4 * i + 2], a2);
        a3 = ffma2(x1.u[1], c[4 * i + 3], a3);
    }
    return hsum2(add2(add2(a0, a1), add2(a2, a3)));
}

// ======================================================================
// Kernel 1: fused softmax(h) + SRWM + FWM recurrence. One CTA per (b,h).
// (EXACT restore of the 801us-best structure.)
// 8 warps: roles 0-3 = SRWM column warps, role 4 (warp 6) = FWM only,
// role 5 (warp 7) = dedicated x-softmax staging.
// One barrier per step (double-buffered broadcast vectors).
// ======================================================================
__global__ __launch_bounds__(256, 2)
void srwm_kernel(const float* __restrict__ h,
                 const float* __restrict__ W_y, const float* __restrict__ W_q,
                 const float* __restrict__ W_k, const float* __restrict__ w_b,
                 const float* __restrict__ sW_y, const float* __restrict__ sW_q,
                 const float* __restrict__ sW_k, const float* __restrict__ sw_b,
                 const float* __restrict__ F0) {
    __shared__ __align__(16) float xs[2][DD];
    __shared__ __align__(16) float q_s[2][DD], k_s[2][DD];
    __shared__ __align__(16) float fq_s[2][DD], fk_s[2][DD], fv_s[2][DD];
    __shared__ __align__(16) float beta_s[2][4];
    __shared__ float fb_s[2];

    const int bh   = blockIdx.x;           // b*NH + h
    const int hh   = bh & (NH - 1);
    const int tid  = threadIdx.x;
    const int warp = tid >> 5;
    const int lane = tid & 31;

    // ---- role / column assignment ----
    int role, e;
    if (warp < 3)            { role = 0; e = warp * 32 + lane; }
    else if (warp == 3) {
        if (lane == 0)       { role = 0; e = 96; }
        else                 { role = 1; e = (lane - 1) & 3; }
    }
    else if (warp == 4)      { role = 2; e = lane; }
    else if (warp == 5)      { role = 3; e = lane; }
    else if (warp == 6)      { role = 4; e = lane; }
    else                     { role = 5; e = lane; }

    const int bidx = (role == 0) ? 0 : (role == 2) ? 1 : (role == 3) ? 2 : 3;

    // ---- initial column load (state + broadcast weight) ----
    u64 c[16];
#pragma unroll
    for (int i = 0; i < 16; i++) c[i] = 0ull;
    if (role <= 4) {
        const float* sp;
        const float* wp = nullptr;
        int stride;
        switch (role) {
            case 0: sp = sW_y + (size_t)bh * DD * YD + e; wp = W_y + (size_t)hh * DD * YD + e; stride = YD; break;
            case 1: sp = sw_b + (size_t)bh * DD * 4  + e; wp = w_b + (size_t)hh * DD * 4  + e; stride = 4;  break;
            case 2: sp = sW_q + (size_t)bh * DD * DD + e; wp = W_q + (size_t)hh * DD * DD + e; stride = DD; break;
            case 3: sp = sW_k + (size_t)bh * DD * DD + e; wp = W_k + (size_t)hh * DD * DD + e; stride = DD; break;
            default: sp = F0  + (size_t)bh * DD * DD + e;                                       stride = DD; break;
        }
#pragma unroll
        for (int i = 0; i < 16; i++) {
            float v0 = sp[(2 * i)     * stride];
            float v1 = sp[(2 * i + 1) * stride];
            if (wp) { v0 += wp[(2 * i) * stride]; v1 += wp[(2 * i + 1) * stride]; }
            c[i] = pack2(v0, v1);
        }
    }

    // ---- prologue: warp 7 computes x_0 = softmax(h_0), prefetches h_1 ----
    const float* hrow = h + (size_t)bh * DD + lane;
    float xreg = 0.0f;
    float* gout = g_fwm + (size_t)bh * DD + lane;
    if (role == 5) {
        float p = __expf(hrow[0]);
        float s = wsum(p);
        xs[0][lane] = __fdividef(p, s);
        xreg = hrow[ROWSTRIDE];
    }
    __syncthreads();

    // ---- peeled interval t = 0: matvec only ----
    if (role <= 3) {
        float yv = dot32v(xs[0], c);
        if (warp == 0)      { float p = __expf(yv); float s = wsum(p); fq_s[0][lane] = __fdividef(p, s); }
        else if (warp == 1) { float p = __expf(yv); float s = wsum(p); fk_s[0][lane] = __fdividef(p, s); }
        else if (warp == 2) { fv_s[0][lane] = yv; }
        else if (warp == 3) { float sg = __fdividef(1.0f, 1.0f + __expf(-yv));
                              if (lane == 0) fb_s[0] = sg;
                              else if (lane <= 4) beta_s[0][e] = sg; }
        else if (warp == 4) { float p = __expf(yv); float s = wsum(p); q_s[0][lane] = __fdividef(p, s); }
        else                { float p = __expf(yv); float s = wsum(p); k_s[0][lane] = __fdividef(p, s); }
    } else if (role == 5) {
        float p = __expf(xreg);
        float s = wsum(p);
        xs[1][lane] = __fdividef(p, s);
        xreg = hrow[(size_t)2 * ROWSTRIDE];
    }
    __syncthreads();

    const u64 neg1 = bcast2(-1.0f);

    // ================= time loop: one barrier per interval =================
    for (int t = 1; t < TT; t++) {
        const int pm = (t - 1) & 1;   // buffers from interval t-1
        const int pc = t & 1;         // buffers produced this interval

        if (role <= 3) {
            const float* qp = q_s[pm];
            const float* kp = k_s[pm];
            const float* xp = xs[pc];
            // scalar chain: s_xk = dot(x_t, k) via lane product + butterfly
            float sxk = wsum(xp[lane] * kp[lane]);
            float bi  = beta_s[pm][bidx];

            // parallel dots on c_old: (q-k)·c and x·c ; keep k for update
            u64 kv[16];
            u64 ad[4] = {0ull, 0ull, 0ull, 0ull};
            u64 ax[4] = {0ull, 0ull, 0ull, 0ull};
#pragma unroll
            for (int i = 0; i < 8; i++) {
                f4u qv = ld4(qp + 4 * i);
                f4u kk = ld4(kp + 4 * i);
                f4u xv = ld4(xp + 4 * i);
                u64 dm0 = ffma2(kk.u[0], neg1, qv.u[0]);   // q - k
                u64 dm1 = ffma2(kk.u[1], neg1, qv.u[1]);
                ad[(2 * i)     & 3] = ffma2(dm0, c[2 * i],     ad[(2 * i)     & 3]);
                ad[(2 * i + 1) & 3] = ffma2(dm1, c[2 * i + 1], ad[(2 * i + 1) & 3]);
                ax[(2 * i)     & 3] = ffma2(xv.u[0], c[2 * i],     ax[(2 * i)     & 3]);
                ax[(2 * i + 1) & 3] = ffma2(xv.u[1], c[2 * i + 1], ax[(2 * i + 1) & 3]);
                kv[2 * i]     = kk.u[0];
                kv[2 * i + 1] = kk.u[1];
            }
            float delta = bi * hsum4(ad);
            float yv    = hsum4(ax) + delta * sxk;

            // activations (critical path) first
            if (warp == 0)      { float p = __expf(yv); float s = wsum(p); fq_s[pc][lane] = __fdividef(p, s); }
            else if (warp == 1) { float p = __expf(yv); float s = wsum(p); fk_s[pc][lane] = __fdividef(p, s); }
            else if (warp == 2) { fv_s[pc][lane] = yv; }
            else if (warp == 3) { float sg = __fdividef(1.0f, 1.0f + __expf(-yv));
                                  if (lane == 0) fb_s[pc] = sg;
                                  else if (lane <= 4) beta_s[pc][e] = sg; }
            else if (warp == 4) { float p = __expf(yv); float s = wsum(p); q_s[pc][lane] = __fdividef(p, s); }
            else                { float p = __expf(yv); float s = wsum(p); k_s[pc][lane] = __fdividef(p, s); }

            // off-path state update
            u64 d2 = bcast2(delta);
#pragma unroll
            for (int i = 0; i < 16; i++) c[i] = ffma2(kv[i], d2, c[i]);
        } else if (role == 4) {
            // ---- warp 6: FWM step t-1 (only task) ----
            const float* fqp = fq_s[pm];
            const float* fkp = fk_s[pm];
            float sqk = wsum(fqp[lane] * fkp[lane]);
            float fb  = fb_s[pm];
            float fvd = fv_s[pm][lane];

            u64 kv[16];
            u64 av[4] = {0ull, 0ull, 0ull, 0ull};
            u64 ao[4] = {0ull, 0ull, 0ull, 0ull};
#pragma unroll
            for (int i = 0; i < 8; i++) {
                f4u fqv = ld4(fqp + 4 * i);
                f4u fkv = ld4(fkp + 4 * i);
                av[(2 * i)     & 3] = ffma2(fkv.u[0], c[2 * i],     av[(2 * i)     & 3]);
                av[(2 * i + 1) & 3] = ffma2(fkv.u[1], c[2 * i + 1], av[(2 * i + 1) & 3]);
                ao[(2 * i)     & 3] = ffma2(fqv.u[0], c[2 * i],     ao[(2 * i)     & 3]);
                ao[(2 * i + 1) & 3] = ffma2(fqv.u[1], c[2 * i + 1], ao[(2 * i + 1) & 3]);
                kv[2 * i]     = fkv.u[0];
                kv[2 * i + 1] = fkv.u[1];
            }
            float vold = hsum4(av);
            float outq = hsum4(ao);
            float delta = fb * (fvd - vold);
            gout[(size_t)(t - 1) * ROWSTRIDE] = outq + delta * sqk;
            u64 d2 = bcast2(delta);
#pragma unroll
            for (int i = 0; i < 16; i++) c[i] = ffma2(kv[i], d2, c[i]);
        } else {
            // ---- warp 7: stage x_{t+1}, prefetch h_{t+2} ----
            float p = __expf(xreg);
            float s = wsum(p);
            xs[(t + 1) & 1][lane] = __fdividef(p, s);
            xreg = (t + 2 < TT) ? hrow[(size_t)(t + 2) * ROWSTRIDE] : 0.0f;
        }
        __syncthreads();
    }

    // ---- epilogue: FWM step TT-1 ----
    if (role == 4) {
        const int pm = (TT - 1) & 1;
        const float* fqp = fq_s[pm];
        const float* fkp = fk_s[pm];
        float sqk = wsum(fqp[lane] * fkp[lane]);
        u64 av[4] = {0ull, 0ull, 0ull, 0ull};
        u64 ao[4] = {0ull, 0ull, 0ull, 0ull};
#pragma unroll
        for (int i = 0; i < 8; i++) {
            f4u fqv = ld4(fqp + 4 * i);
            f4u fkv = ld4(fkp + 4 * i);
            av[(2 * i)     & 3] = ffma2(fkv.u[0], c[2 * i],     av[(2 * i)     & 3]);
            av[(2 * i + 1) & 3] = ffma2(fkv.u[1], c[2 * i + 1], av[(2 * i + 1) & 3]);
            ao[(2 * i)     & 3] = ffma2(fqv.u[0], c[2 * i],     ao[(2 * i)     & 3]);
            ao[(2 * i + 1) & 3] = ffma2(fqv.u[1], c[2 * i + 1], ao[(2 * i + 1) & 3]);
        }
        float vold = hsum4(av);
        float outq = hsum4(ao);
        float delta = fb_s[pm] * (fv_s[pm][lane] - vold);
        gout[(size_t)(TT - 1) * ROWSTRIDE] = outq + delta * sqk;
    }
}

// ======================================================================
// Kernel 2: out = h + g_fwm @ W_out^T    (M=32768, N=256, K=256)
// BM=128, BN=128, BK=16, 256 threads, 8x8 f32x2 thread tile,
// 2-stage double-buffered smem, one __syncthreads per k-tile.
// ======================================================================
#define GBM 128
#define GBN 128
#define GBK 16
#define ALDA (GBM + 4)
#define BLDA (GBN + 4)

__global__ __launch_bounds__(256)
void out_gemm_kernel(const float* __restrict__ W,   // W_out [n][k], 256x256
                     const float* __restrict__ h,
                     float* __restrict__ out) {
    __shared__ __align__(16) float As[2][GBK][ALDA];
    __shared__ __align__(16) float Bs[2][GBK][BLDA];

    const int tid = threadIdx.x;
    const int m0  = blockIdx.x * GBM;
    const int n0  = blockIdx.y * GBN;
    const int ty  = tid >> 4;    // 0..15 -> m sub-tile (8 rows)
    const int tx  = tid & 15;    // 0..15 -> n sub-tile (8 cols)

    // A tile: 128 rows x 16 k = 512 float4 -> 2 per thread; B same.
    const int a_row = tid >> 2;          // 0..63 (x2 groups of 64)
    const int a_kv  = (tid & 3) * 4;     // k offset 0..12

    u64 acc[8][4];
#pragma unroll
    for (int i = 0; i < 8; i++) {
        acc[i][0] = 0ull; acc[i][1] = 0ull; acc[i][2] = 0ull; acc[i][3] = 0ull;
    }

    const int NT = INDIM / GBK;   // 16 k-tiles

    float4 ar[2], br[2];
    // --- prologue: load tile 0 ---
#pragma unroll
    for (int r = 0; r < 2; r++) {
        ar[r] = *(const float4*)(g_fwm + (size_t)(m0 + a_row + r * 64) * INDIM + a_kv);
        br[r] = *(const float4*)(W + (size_t)(n0 + a_row + r * 64) * INDIM + a_kv);
    }
#pragma unroll
    for (int r = 0; r < 2; r++) {
        int row = a_row + r * 64;
        As[0][a_kv + 0][row] = ar[r].x; As[0][a_kv + 1][row] = ar[r].y;
        As[0][a_kv + 2][row] = ar[r].z; As[0][a_kv + 3][row] = ar[r].w;
        Bs[0][a_kv + 0][row] = br[r].x; Bs[0][a_kv + 1][row] = br[r].y;
        Bs[0][a_kv + 2][row] = br[r].z; Bs[0][a_kv + 3][row] = br[r].w;
    }
    __syncthreads();

    for (int kt = 0; kt < NT; kt++) {
        const int s = kt & 1;
        // prefetch next tile into registers
        if (kt + 1 < NT) {
            const int ko = (kt + 1) * GBK;
#pragma unroll
            for (int r = 0; r < 2; r++) {
                ar[r] = *(const float4*)(g_fwm + (size_t)(m0 + a_row + r * 64) * INDIM + ko + a_kv);
                br[r] = *(const float4*)(W + (size_t)(n0 + a_row + r * 64) * INDIM + ko + a_kv);
            }
        }
        // compute on stage s
#pragma unroll
        for (int k = 0; k < GBK; k++) {
            f4u a0 = ld4(&As[s][k][ty * 8]);
            f4u a1 = ld4(&As[s][k][ty * 8 + 4]);
            f4u b0 = ld4(&Bs[s][k][tx * 8]);
            f4u b1 = ld4(&Bs[s][k][tx * 8 + 4]);
            float av[8];
            av[0] = a0.f.x; av[1] = a0.f.y; av[2] = a0.f.z; av[3] = a0.f.w;
            av[4] = a1.f.x; av[5] = a1.f.y; av[6] = a1.f.z; av[7] = a1.f.w;
#pragma unroll
            for (int i = 0; i < 8; i++) {
                u64 p = bcast2(av[i]);
                acc[i][0] = ffma2(p, b0.u[0], acc[i][0]);
                acc[i][1] = ffma2(p, b0.u[1], acc[i][1]);
                acc[i][2] = ffma2(p, b1.u[0], acc[i][2]);
                acc[i][3] = ffma2(p, b1.u[1], acc[i][3]);
            }
        }
        // store prefetched tile into the other stage
        if (kt + 1 < NT) {
            const int d = s ^ 1;
#pragma unroll
            for (int r = 0; r < 2; r++) {
                int row = a_row + r * 64;
                As[d][a_kv + 0][row] = ar[r].x; As[d][a_kv + 1][row] = ar[r].y;
                As[d][a_kv + 2][row] = ar[r].z; As[d][a_kv + 3][row] = ar[r].w;
                Bs[d][a_kv + 0][row] = br[r].x; Bs[d][a_kv + 1][row] = br[r].y;
                Bs[d][a_kv + 2][row] = br[r].z; Bs[d][a_kv + 3][row] = br[r].w;
            }
            __syncthreads();
        }
    }

    // epilogue: residual add + store (8 rows x 8 cols per thread)
#pragma unroll
    for (int i = 0; i < 8; i++) {
        int row = m0 + ty * 8 + i;
        const float* hp = h + (size_t)row * INDIM + n0 + tx * 8;
        float* op = out + (size_t)row * INDIM + n0 + tx * 8;
        float4 hv0 = *(const float4*)hp;
        float4 hv1 = *(const float4*)(hp + 4);
        float v0, v1, v2, v3, v4, v5, v6, v7;
        asm("mov.b64 {%0, %1}, %2;" : "=f"(v0), "=f"(v1) : "l"(acc[i][0]));
        asm("mov.b64 {%0, %1}, %2;" : "=f"(v2), "=f"(v3) : "l"(acc[i][1]));
        asm("mov.b64 {%0, %1}, %2;" : "=f"(v4), "=f"(v5) : "l"(acc[i][2]));
        asm("mov.b64 {%0, %1}, %2;" : "=f"(v6), "=f"(v7) : "l"(acc[i][3]));
        float4 o0, o1;
        o0.x = hv0.x + v0; o0.y = hv0.y + v1; o0.z = hv0.z + v2; o0.w = hv0.w + v3;
        o1.x = hv1.x + v4; o1.y = hv1.y + v5; o1.z = hv1.z + v6; o1.w = hv1.w + v7;
        *(float4*)op = o0;
        *(float4*)(op + 4) = o1;
    }
}

// ======================================================================
extern "C" void kernel_launch(void* const* d_in, const int* in_sizes, int n_in,
                              void* d_out, int out_size) {
    const float* h     = (const float*)d_in[0];
    const float* W_y   = (const float*)d_in[1];
    const float* W_q   = (const float*)d_in[2];
    const float* W_k   = (const float*)d_in[3];
    const float* w_b   = (const float*)d_in[4];
    const float* W_out = (const float*)d_in[5];
    const float* sW_y  = (const float*)d_in[6];
    const float* sW_q  = (const float*)d_in[7];
    const float* sW_k  = (const float*)d_in[8];
    const float* sw_b  = (const float*)d_in[9];
    const float* F0    = (const float*)d_in[10];
    float* out = (float*)d_out;

    srwm_kernel<<<BB * NH, 256>>>(h, W_y, W_q, W_k, w_b, sW_y, sW_q, sW_k, sw_b, F0);

    dim3 ggrid((TT * BB) / GBM, INDIM / GBN);
    out_gemm_kernel<<<ggrid, 256>>>(W_out, h, out);
}